// round 10
// baseline (speedup 1.0000x reference)
#include <cuda_runtime.h>
#include <mma.h>
#include <cstdint>

using namespace nvcuda;

// NOTE (environment pitfalls, confirmed):
//  - Harness PTX targets sm_103 (no 'a'): tcgen05/TMEM rejected by ptxas.
//    Legacy mma.sync (HMMA) is the usable tensor engine.
//  - 128MB static __device__ globals poison the run (rounds 2/3). Keep
//    scratch small; cp.async itself is fine (round 9 passed with it).
//  - GEMM is smem-crossbar-bound at 8 warps/4x2; this round: 4 warps/2x2
//    64x64 warp tiles to cut LDS redundancy (48KB -> 32KB per stage).

// ---------------- problem constants ----------------
#define BQ 4
#define LQ 8192
#define DQ 1024
#define NHQ 16
#define HDQ 64
#define MT (BQ * LQ)          // 32768 rows
#define ROW_TILES (MT / 128)  // 256
#define COL_TILES (DQ / 128)  // 8
#define NT 64                 // k-stages of 16

// ---------------- device scratch (no allocations allowed) ----------------
__device__ __align__(16) float g_Wv_sumT[NHQ * DQ];  // [head][k]
__device__ __align__(16) float g_bv_sum[NHQ];
__device__ __align__(16) int   g_mask[MT];
__device__ int   g_mask_kind;
__device__ __align__(16) float g_sv[MT * NHQ];
__device__ __align__(16) float g_partial[ROW_TILES * DQ];
__device__ __align__(16) float g_kv_sum[BQ * DQ];

__device__ __forceinline__ float phi_fn(float x) {
    return x > 0.f ? x + 1.f : __expf(x);   // elu(x)+1
}
__device__ __forceinline__ float rtf(float x) { return wmma::__float_to_tf32(x); }

// ---------------- mask dtype detection + normalization ----------------
__global__ void detect_mask_kernel(const unsigned int* m) {
    __shared__ int f_nonbin, f_float;
    if (threadIdx.x == 0) { f_nonbin = 0; f_float = 0; }
    __syncthreads();
    int nb = 0, fl = 0;
    for (int i = threadIdx.x; i < 8192; i += 256) {
        unsigned v = m[i];
        if (v == 0x3F800000u) fl = 1;
        else if (v > 1u) nb = 1;
    }
    if (fl) atomicOr(&f_float, 1);
    if (nb) atomicOr(&f_nonbin, 1);
    __syncthreads();
    if (threadIdx.x == 0) g_mask_kind = f_float ? 2 : (f_nonbin ? 1 : 0);
}

__global__ void normalize_mask_kernel(const void* m) {
    int i = blockIdx.x * 256 + threadIdx.x;
    if (i >= MT) return;
    int kind = g_mask_kind;
    int v;
    if (kind == 2)      v = (((const float*)m)[i] != 0.0f);
    else if (kind == 1) v = (((const unsigned char*)m)[i] != 0);
    else                v = (((const int*)m)[i] != 0);
    g_mask[i] = v;
}

// ---------------- Wv column sums per head (transposed) ----------------
__global__ void wvsum_kernel(const float* __restrict__ Wv,
                             const float* __restrict__ bv) {
    int t = blockIdx.x * 256 + threadIdx.x;
    if (t < DQ * NHQ) {
        int k = t >> 4, n = t & 15;
        const float* p = Wv + (size_t)k * DQ + n * HDQ;
        float s = 0.f;
        #pragma unroll 8
        for (int v = 0; v < HDQ; v++) s += p[v];
        g_Wv_sumT[n * DQ + k] = s;
    }
    if (t < NHQ) {
        const float* p = bv + t * HDQ;
        float s = 0.f;
        #pragma unroll 8
        for (int v = 0; v < HDQ; v++) s += p[v];
        g_bv_sum[t] = s;
    }
}

// ---------------- sv pre-pass (round-5 proven) ----------------
__global__ void __launch_bounds__(256) sv_kernel(const float* __restrict__ X) {
    extern __shared__ __align__(16) float4 sWv[];
    const int tid = threadIdx.x;
    {
        const float4* src = (const float4*)g_Wv_sumT;
        #pragma unroll
        for (int i = 0; i < NHQ * DQ / 4 / 256; i++)
            sWv[i * 256 + tid] = src[i * 256 + tid];
    }
    __syncthreads();

    const int warp = tid >> 5, lane = tid & 31;
    const int row0 = blockIdx.x * 32 + warp * 4;
    const float4* x0 = (const float4*)(X + (size_t)row0 * DQ);
    const float4* x1 = (const float4*)(X + (size_t)(row0 + 1) * DQ);
    const float4* x2 = (const float4*)(X + (size_t)(row0 + 2) * DQ);
    const float4* x3 = (const float4*)(X + (size_t)(row0 + 3) * DQ);

    float acc[4][NHQ];
    #pragma unroll
    for (int p = 0; p < 4; p++)
        #pragma unroll
        for (int h = 0; h < NHQ; h++) acc[p][h] = 0.f;

    for (int c = lane; c < DQ / 4; c += 32) {
        float4 xv0 = x0[c], xv1 = x1[c], xv2 = x2[c], xv3 = x3[c];
        #pragma unroll
        for (int h = 0; h < NHQ; h++) {
            float4 w = sWv[h * (DQ / 4) + c];
            acc[0][h] += xv0.x * w.x + xv0.y * w.y + xv0.z * w.z + xv0.w * w.w;
            acc[1][h] += xv1.x * w.x + xv1.y * w.y + xv1.z * w.z + xv1.w * w.w;
            acc[2][h] += xv2.x * w.x + xv2.y * w.y + xv2.z * w.z + xv2.w * w.w;
            acc[3][h] += xv3.x * w.x + xv3.y * w.y + xv3.z * w.z + xv3.w * w.w;
        }
    }
    #pragma unroll
    for (int off = 16; off; off >>= 1)
        #pragma unroll
        for (int p = 0; p < 4; p++)
            #pragma unroll
            for (int h = 0; h < NHQ; h++)
                acc[p][h] += __shfl_xor_sync(0xffffffffu, acc[p][h], off);
    if (lane < NHQ) {
        float bvs = g_bv_sum[lane];
        #pragma unroll
        for (int p = 0; p < 4; p++) {
            int m = g_mask[row0 + p];
            g_sv[(size_t)(row0 + p) * NHQ + lane] = m ? 0.f : acc[p][lane] + bvs;
        }
    }
}

// ---------------- main GEMM: 128x128 CTA tile, 64x64 warp tiles, 128 thr ----
#define STAGES 4
#define AS_LD 20
#define BS_LD 132
#define A_STG (128 * AS_LD)                   // 2560 floats per A stage
#define B_STG (16 * BS_LD)                    // 2112 floats per B stage
#define B_BASE (STAGES * A_STG)               // 10240
#define SMEM_FLOATS (B_BASE + STAGES * B_STG) // 18688 floats = 74752 B
#define CT_LD 68

__device__ __forceinline__ void cp16(uint32_t dst, const float* src) {
    asm volatile("cp.async.cg.shared.global [%0], [%1], 16;" :: "r"(dst), "l"(src));
}
__device__ __forceinline__ void cp_commit() {
    asm volatile("cp.async.commit_group;");
}
__device__ __forceinline__ void cp_wait2() {
    asm volatile("cp.async.wait_group 2;");
}

template <int MODE>
__global__ void __launch_bounds__(128, 2)
gemm_kernel(const float* __restrict__ X, const float* __restrict__ W,
            const float* __restrict__ bias, float* __restrict__ outp) {
    extern __shared__ __align__(16) float ds[];
    __shared__ float svred[256];
    __shared__ float red2[128];

    const int tid = threadIdx.x;
    const int bn = blockIdx.x;   // column tile (128 cols = 2 heads)
    const int br = blockIdx.y;   // row tile

    const float* Ab = X + (size_t)br * 128 * DQ;
    const float* Bb = W + bn * 128;

    // cp.async mapping: 8 x 16B per thread per stage
    // A: one row per thread (128 rows), 4 chunks of 4 floats
    const int ar = tid;
    const float* srcA = Ab + (size_t)ar * DQ;
    // B: 16 rows x 8 thread-cols of 16 floats
    const int brr = tid >> 3, bc = (tid & 7) * 16;
    const float* srcB = Bb + (size_t)brr * DQ + bc;

    uint32_t smem_base = (uint32_t)__cvta_generic_to_shared(ds);
    uint32_t dA = smem_base + (uint32_t)(ar * AS_LD) * 4u;
    uint32_t dB = smem_base + (uint32_t)(B_BASE + brr * BS_LD + bc) * 4u;

    #define ISSUE_STAGE(slot, kt) do {                                           \
        uint32_t _ao = (uint32_t)(slot) * (A_STG * 4u);                           \
        uint32_t _bo = (uint32_t)(slot) * (B_STG * 4u);                           \
        cp16(dA + _ao,       srcA + (kt));                                        \
        cp16(dA + _ao + 16,  srcA + (kt) + 4);                                    \
        cp16(dA + _ao + 32,  srcA + (kt) + 8);                                    \
        cp16(dA + _ao + 48,  srcA + (kt) + 12);                                   \
        cp16(dB + _bo,       srcB + (size_t)(kt) * DQ);                           \
        cp16(dB + _bo + 16,  srcB + (size_t)(kt) * DQ + 4);                       \
        cp16(dB + _bo + 32,  srcB + (size_t)(kt) * DQ + 8);                       \
        cp16(dB + _bo + 48,  srcB + (size_t)(kt) * DQ + 12);                      \
        cp_commit(); } while (0)

    ISSUE_STAGE(0, 0);
    ISSUE_STAGE(1, 16);
    ISSUE_STAGE(2, 32);

    const int wid = tid >> 5;
    const int wm = wid & 1;    // warp rows wm*64..+63
    const int wn = wid >> 1;   // warp cols wn*64..+63

    wmma::fragment<wmma::accumulator, 16, 16, 8, float> fc[4][4];
    #pragma unroll
    for (int i = 0; i < 4; i++)
        #pragma unroll
        for (int j = 0; j < 4; j++)
            wmma::fill_fragment(fc[i][j], 0.f);

    for (int t = 0; t < NT; t++) {
        cp_wait2();
        __syncthreads();
        if (t + 3 < NT) {
            ISSUE_STAGE((t + 3) & 3, (t + 3) * 16);
        } else {
            cp_commit();   // empty group keeps wait_group accounting uniform
        }

        const float* As = ds + (t & 3) * A_STG;
        const float* Bs = ds + B_BASE + (t & 3) * B_STG;
        #pragma unroll
        for (int kk = 0; kk < 2; kk++) {
            wmma::fragment<wmma::matrix_a, 16, 16, 8, wmma::precision::tf32, wmma::row_major> fa[4];
            wmma::fragment<wmma::matrix_b, 16, 16, 8, wmma::precision::tf32, wmma::row_major> fb[4];
            #pragma unroll
            for (int i = 0; i < 4; i++) {
                wmma::load_matrix_sync(fa[i], &As[(wm * 64 + i * 16) * AS_LD + kk * 8], AS_LD);
                #pragma unroll
                for (int e = 0; e < fa[i].num_elements; e++)
                    fa[i].x[e] = rtf(fa[i].x[e]);      // RN tf32 in-register
            }
            #pragma unroll
            for (int j = 0; j < 4; j++) {
                wmma::load_matrix_sync(fb[j], &Bs[(kk * 8) * BS_LD + wn * 64 + j * 16], BS_LD);
                #pragma unroll
                for (int e = 0; e < fb[j].num_elements; e++)
                    fb[j].x[e] = rtf(fb[j].x[e]);
            }
            #pragma unroll
            for (int i = 0; i < 4; i++)
                #pragma unroll
                for (int j = 0; j < 4; j++)
                    wmma::mma_sync(fc[i][j], fa[i], fb[j], fc[i][j]);
        }
        __syncthreads();
    }
    __syncthreads();

    // ---- epilogue: two 64-col halves through smem Ct (128 x CT_LD) ----
    if (MODE == 0) {
        // all 128 threads: load sv pair for their row
        float2 s = *(const float2*)(g_sv + (size_t)(br * 128 + tid) * NHQ + bn * 2);
        svred[tid * 2 + 0] = s.x;
        svred[tid * 2 + 1] = s.y;
    }

    #pragma unroll
    for (int hh = 0; hh < 2; hh++) {
        __syncthreads();
        if (wn == hh) {
            #pragma unroll
            for (int i = 0; i < 4; i++)
                #pragma unroll
                for (int j = 0; j < 4; j++)
                    wmma::store_matrix_sync(&ds[(wm * 64 + i * 16) * CT_LD + j * 16],
                                            fc[i][j], CT_LD, wmma::mem_row_major);
        }
        __syncthreads();
        const int c = tid & 63, rg = tid >> 6;   // rg in {0,1}
        const float bias_c = bias[bn * 128 + hh * 64 + c];
        if (MODE == 0) {
            float part = 0.f;
            #pragma unroll 8
            for (int r = rg; r < 128; r += 2)
                part += phi_fn(ds[r * CT_LD + c] + bias_c) * svred[r * 2 + hh];
            red2[rg * 64 + c] = part;
            __syncthreads();
            if (tid < 64)
                g_partial[(size_t)br * DQ + bn * 128 + hh * 64 + tid] =
                    red2[tid] + red2[64 + tid];
        } else {
            const int gcol = bn * 128 + hh * 64 + c;
            const float kvs = g_kv_sum[(br >> 6) * DQ + gcol];
            #pragma unroll 8
            for (int r = rg; r < 128; r += 2)
                outp[(size_t)(br * 128 + r) * DQ + gcol] =
                    phi_fn(ds[r * CT_LD + c] + bias_c) * kvs;
        }
    }
    #undef ISSUE_STAGE
}

// ---------------- deterministic reduction of per-tile partials ----------------
__global__ void kvreduce_kernel() {
    int t = blockIdx.x * 256 + threadIdx.x;
    if (t >= BQ * DQ) return;
    int b = t >> 10, c = t & 1023;
    const float* p = g_partial + (size_t)(b * 64) * DQ + c;
    float s = 0.f;
    #pragma unroll 8
    for (int j = 0; j < 64; j++) s += p[(size_t)j * DQ];
    g_kv_sum[t] = s;
}

// ---------------- entry point ----------------
extern "C" void kernel_launch(void* const* d_in, const int* in_sizes, int n_in,
                              void* d_out, int out_size) {
    const float* query = (const float*)d_in[0];
    const void*  mask  = d_in[1];
    const float* Wq    = (const float*)d_in[2];
    const float* bq    = (const float*)d_in[3];
    const float* Wk    = (const float*)d_in[4];
    const float* bk    = (const float*)d_in[5];
    const float* Wv    = (const float*)d_in[6];
    const float* bv    = (const float*)d_in[7];
    float* out = (float*)d_out;

    const int sv_smem = NHQ * DQ * 4;        // 64KB
    const int gemm_smem = SMEM_FLOATS * 4;   // 74752B
    cudaFuncSetAttribute(sv_kernel, cudaFuncAttributeMaxDynamicSharedMemorySize, sv_smem);
    cudaFuncSetAttribute(gemm_kernel<0>, cudaFuncAttributeMaxDynamicSharedMemorySize, gemm_smem);
    cudaFuncSetAttribute(gemm_kernel<1>, cudaFuncAttributeMaxDynamicSharedMemorySize, gemm_smem);

    detect_mask_kernel<<<1, 256>>>((const unsigned int*)mask);
    normalize_mask_kernel<<<MT / 256, 256>>>(mask);
    wvsum_kernel<<<(DQ * NHQ + 255) / 256, 256>>>(Wv, bv);
    sv_kernel<<<MT / 32, 256, sv_smem>>>(query);
    gemm_kernel<0><<<dim3(COL_TILES, ROW_TILES), 128, gemm_smem>>>(query, Wk, bk, nullptr);
    kvreduce_kernel<<<(BQ * DQ + 255) / 256, 256>>>();
    gemm_kernel<1><<<dim3(COL_TILES, ROW_TILES), 128, gemm_smem>>>(query, Wq, bq, out);
}

// round 12
// speedup vs baseline: 2.8837x; 2.8837x over previous
#include <cuda_runtime.h>
#include <cuda_fp16.h>
#include <mma.h>
#include <cstdint>

using namespace nvcuda;

// NOTE (environment pitfalls, confirmed):
//  - Harness PTX targets sm_103 (no 'a'): tcgen05/TMEM rejected by ptxas.
//    Legacy mma.sync (HMMA) is the usable tensor engine.
//  - 128MB static __device__ globals poison the run. Keep scratch small.
//  - Schedule experiments (cp.async, 4-warp, 256-wide tiles) all lost to the
//    round-5 shape: 8 warps, 128x128 tile, double-buffered sync loads,
//    2 CTAs/SM. This round keeps that shape and switches tf32 -> fp16
//    (same 10-bit mantissa => same error; 2x MMA rate, half the smem bytes).

// ---------------- problem constants ----------------
#define BQ 4
#define LQ 8192
#define DQ 1024
#define NHQ 16
#define HDQ 64
#define MT (BQ * LQ)          // 32768 rows
#define ROW_TILES (MT / 128)  // 256
#define COL_TILES (DQ / 128)  // 8
#define NT 64                 // k-stages of 16

// ---------------- device scratch (no allocations allowed) ----------------
__device__ __align__(16) float g_Wv_sumT[NHQ * DQ];  // [head][k]
__device__ __align__(16) float g_bv_sum[NHQ];
__device__ __align__(16) int   g_mask[MT];
__device__ int   g_mask_kind;
__device__ __align__(16) float g_sv[MT * NHQ];
__device__ __align__(16) float g_partial[ROW_TILES * DQ];
__device__ __align__(16) float g_kv_sum[BQ * DQ];

__device__ __forceinline__ float phi_fn(float x) {
    return x > 0.f ? x + 1.f : __expf(x);   // elu(x)+1
}

// ---------------- mask dtype detection + normalization ----------------
__global__ void detect_mask_kernel(const unsigned int* m) {
    __shared__ int f_nonbin, f_float;
    if (threadIdx.x == 0) { f_nonbin = 0; f_float = 0; }
    __syncthreads();
    int nb = 0, fl = 0;
    for (int i = threadIdx.x; i < 8192; i += 256) {
        unsigned v = m[i];
        if (v == 0x3F800000u) fl = 1;
        else if (v > 1u) nb = 1;
    }
    if (fl) atomicOr(&f_float, 1);
    if (nb) atomicOr(&f_nonbin, 1);
    __syncthreads();
    if (threadIdx.x == 0) g_mask_kind = f_float ? 2 : (f_nonbin ? 1 : 0);
}

__global__ void normalize_mask_kernel(const void* m) {
    int i = blockIdx.x * 256 + threadIdx.x;
    if (i >= MT) return;
    int kind = g_mask_kind;
    int v;
    if (kind == 2)      v = (((const float*)m)[i] != 0.0f);
    else if (kind == 1) v = (((const unsigned char*)m)[i] != 0);
    else                v = (((const int*)m)[i] != 0);
    g_mask[i] = v;
}

// ---------------- Wv column sums per head (transposed) ----------------
__global__ void wvsum_kernel(const float* __restrict__ Wv,
                             const float* __restrict__ bv) {
    int t = blockIdx.x * 256 + threadIdx.x;
    if (t < DQ * NHQ) {
        int k = t >> 4, n = t & 15;
        const float* p = Wv + (size_t)k * DQ + n * HDQ;
        float s = 0.f;
        #pragma unroll 8
        for (int v = 0; v < HDQ; v++) s += p[v];
        g_Wv_sumT[n * DQ + k] = s;
    }
    if (t < NHQ) {
        const float* p = bv + t * HDQ;
        float s = 0.f;
        #pragma unroll 8
        for (int v = 0; v < HDQ; v++) s += p[v];
        g_bv_sum[t] = s;
    }
}

// ---------------- sv pre-pass (round-5 proven) ----------------
__global__ void __launch_bounds__(256) sv_kernel(const float* __restrict__ X) {
    extern __shared__ __align__(16) float4 sWv[];
    const int tid = threadIdx.x;
    {
        const float4* src = (const float4*)g_Wv_sumT;
        #pragma unroll
        for (int i = 0; i < NHQ * DQ / 4 / 256; i++)
            sWv[i * 256 + tid] = src[i * 256 + tid];
    }
    __syncthreads();

    const int warp = tid >> 5, lane = tid & 31;
    const int row0 = blockIdx.x * 32 + warp * 4;
    const float4* x0 = (const float4*)(X + (size_t)row0 * DQ);
    const float4* x1 = (const float4*)(X + (size_t)(row0 + 1) * DQ);
    const float4* x2 = (const float4*)(X + (size_t)(row0 + 2) * DQ);
    const float4* x3 = (const float4*)(X + (size_t)(row0 + 3) * DQ);

    float acc[4][NHQ];
    #pragma unroll
    for (int p = 0; p < 4; p++)
        #pragma unroll
        for (int h = 0; h < NHQ; h++) acc[p][h] = 0.f;

    for (int c = lane; c < DQ / 4; c += 32) {
        float4 xv0 = x0[c], xv1 = x1[c], xv2 = x2[c], xv3 = x3[c];
        #pragma unroll
        for (int h = 0; h < NHQ; h++) {
            float4 w = sWv[h * (DQ / 4) + c];
            acc[0][h] += xv0.x * w.x + xv0.y * w.y + xv0.z * w.z + xv0.w * w.w;
            acc[1][h] += xv1.x * w.x + xv1.y * w.y + xv1.z * w.z + xv1.w * w.w;
            acc[2][h] += xv2.x * w.x + xv2.y * w.y + xv2.z * w.z + xv2.w * w.w;
            acc[3][h] += xv3.x * w.x + xv3.y * w.y + xv3.z * w.z + xv3.w * w.w;
        }
    }
    #pragma unroll
    for (int off = 16; off; off >>= 1)
        #pragma unroll
        for (int p = 0; p < 4; p++)
            #pragma unroll
            for (int h = 0; h < NHQ; h++)
                acc[p][h] += __shfl_xor_sync(0xffffffffu, acc[p][h], off);
    if (lane < NHQ) {
        float bvs = g_bv_sum[lane];
        #pragma unroll
        for (int p = 0; p < 4; p++) {
            int m = g_mask[row0 + p];
            g_sv[(size_t)(row0 + p) * NHQ + lane] = m ? 0.f : acc[p][lane] + bvs;
        }
    }
}

// ---------------- main GEMM: 128x128 tile, fp16 HMMA, round-5 schedule ----
// Stages are __half: A 128x(16 pad 24), B 16x(128 pad 136). Double buffered.
#define AS_LDH 24
#define BS_LDH 136
#define A_STG_H (128 * AS_LDH)               // 3072 halves
#define B_STG_H (16 * BS_LDH)                // 2176 halves
#define B_BASE_H (2 * A_STG_H)               // 6144
#define STAGE_TOTAL_H (B_BASE_H + 2 * B_STG_H) // 10496 halves = 20992 B
#define CT_LD 68
#define GSMEM_B (128 * CT_LD * 4)            // 34816 B (union covers stages)

__device__ __forceinline__ void st_half4(__half* p, float4 v) {
    __half2 h01 = __floats2half2_rn(v.x, v.y);
    __half2 h23 = __floats2half2_rn(v.z, v.w);
    uint2 u;
    u.x = *reinterpret_cast<const uint32_t*>(&h01);
    u.y = *reinterpret_cast<const uint32_t*>(&h23);
    *reinterpret_cast<uint2*>(p) = u;
}

template <int MODE>
__global__ void __launch_bounds__(256, 2)
gemm_kernel(const float* __restrict__ X, const float* __restrict__ W,
            const float* __restrict__ bias, float* __restrict__ outp) {
    extern __shared__ __align__(16) char ds[];
    __half* hs = (__half*)ds;            // stages
    float*  Ct = (float*)ds;             // epilogue union
    __shared__ float svred[256];
    __shared__ float red2[256];

    const int tid = threadIdx.x;
    const int bn = blockIdx.x;   // column tile (128 cols = 2 heads)
    const int br = blockIdx.y;   // row tile

    const float* Ab = X + (size_t)br * 128 * DQ;
    const float* Bb = W + bn * 128;

    // A staging: thread owns rows {ar, ar+64}, k-offset ac4*4..+3
    const int ar = tid >> 2, ac4 = tid & 3;
    // B staging: thread owns rows {brr, brr+8}, col-offset bc4*4..+3
    const int brr = tid >> 5, bc4 = tid & 31;

    const int wid = tid >> 5;
    const int wm = wid & 3;       // warp rows wm*32 .. +31
    const int wn = wid >> 2;      // warp cols wn*64 .. +63

    wmma::fragment<wmma::accumulator, 16, 16, 16, float> fc[2][4];
    #pragma unroll
    for (int i = 0; i < 2; i++)
        #pragma unroll
        for (int j = 0; j < 4; j++)
            wmma::fill_fragment(fc[i][j], 0.f);

    // ---- preload stage 0 ----
    {
        float4 a0 = *(const float4*)(Ab + (size_t)ar * DQ + ac4 * 4);
        float4 a1 = *(const float4*)(Ab + (size_t)(ar + 64) * DQ + ac4 * 4);
        float4 b0 = *(const float4*)(Bb + (size_t)brr * DQ + bc4 * 4);
        float4 b1 = *(const float4*)(Bb + (size_t)(brr + 8) * DQ + bc4 * 4);
        st_half4(hs + ar * AS_LDH + ac4 * 4, a0);
        st_half4(hs + (ar + 64) * AS_LDH + ac4 * 4, a1);
        st_half4(hs + B_BASE_H + brr * BS_LDH + bc4 * 4, b0);
        st_half4(hs + B_BASE_H + (brr + 8) * BS_LDH + bc4 * 4, b1);
    }
    __syncthreads();

    int buf = 0;
    for (int t = 0; t < NT; t++) {
        float4 na0, na1, nb0, nb1;
        if (t < NT - 1) {
            const int ko = (t + 1) * 16;
            na0 = *(const float4*)(Ab + (size_t)ar * DQ + ko + ac4 * 4);
            na1 = *(const float4*)(Ab + (size_t)(ar + 64) * DQ + ko + ac4 * 4);
            nb0 = *(const float4*)(Bb + (size_t)(ko + brr) * DQ + bc4 * 4);
            nb1 = *(const float4*)(Bb + (size_t)(ko + brr + 8) * DQ + bc4 * 4);
        }

        // compute on stage[buf]: one K=16 wmma step
        {
            const __half* As = hs + buf * A_STG_H;
            const __half* Bs = hs + B_BASE_H + buf * B_STG_H;
            wmma::fragment<wmma::matrix_a, 16, 16, 16, __half, wmma::row_major> fa[2];
            wmma::fragment<wmma::matrix_b, 16, 16, 16, __half, wmma::row_major> fb[4];
            #pragma unroll
            for (int i = 0; i < 2; i++)
                wmma::load_matrix_sync(fa[i], As + (wm * 32 + i * 16) * AS_LDH, AS_LDH);
            #pragma unroll
            for (int j = 0; j < 4; j++)
                wmma::load_matrix_sync(fb[j], Bs + wn * 64 + j * 16, BS_LDH);
            #pragma unroll
            for (int i = 0; i < 2; i++)
                #pragma unroll
                for (int j = 0; j < 4; j++)
                    wmma::mma_sync(fc[i][j], fa[i], fb[j], fc[i][j]);
        }

        if (t < NT - 1) {
            const int nbuf = buf ^ 1;
            st_half4(hs + nbuf * A_STG_H + ar * AS_LDH + ac4 * 4, na0);
            st_half4(hs + nbuf * A_STG_H + (ar + 64) * AS_LDH + ac4 * 4, na1);
            st_half4(hs + B_BASE_H + nbuf * B_STG_H + brr * BS_LDH + bc4 * 4, nb0);
            st_half4(hs + B_BASE_H + nbuf * B_STG_H + (brr + 8) * BS_LDH + bc4 * 4, nb1);
        }
        __syncthreads();
        buf ^= 1;
    }

    // ---- epilogue (identical math to round 5) ----
    if (MODE == 0) {
        if (tid < 128) {
            float2 s = *(const float2*)(g_sv + (size_t)(br * 128 + tid) * NHQ + bn * 2);
            svred[tid * 2 + 0] = s.x;
            svred[tid * 2 + 1] = s.y;
        }
        #pragma unroll
        for (int hh = 0; hh < 2; hh++) {
            __syncthreads();
            if (wn == hh) {
                #pragma unroll
                for (int i = 0; i < 2; i++)
                    #pragma unroll
                    for (int j = 0; j < 4; j++)
                        wmma::store_matrix_sync(&Ct[(wm * 32 + i * 16) * CT_LD + j * 16],
                                                fc[i][j], CT_LD, wmma::mem_row_major);
            }
            __syncthreads();
            int c = tid & 63, rg = tid >> 6;
            float bias_c = bias[bn * 128 + hh * 64 + c];
            float part = 0.f;
            #pragma unroll 8
            for (int r = rg; r < 128; r += 4) {
                float x = Ct[r * CT_LD + c] + bias_c;
                part += phi_fn(x) * svred[r * 2 + hh];
            }
            red2[rg * 64 + c] = part;
            __syncthreads();
            if (tid < 64) {
                float tot = red2[tid] + red2[64 + tid] + red2[128 + tid] + red2[192 + tid];
                g_partial[(size_t)br * DQ + bn * 128 + hh * 64 + tid] = tot;
            }
        }
    } else {
        int b = br >> 6;
        #pragma unroll
        for (int hh = 0; hh < 2; hh++) {
            __syncthreads();
            if (wn == hh) {
                #pragma unroll
                for (int i = 0; i < 2; i++)
                    #pragma unroll
                    for (int j = 0; j < 4; j++)
                        wmma::store_matrix_sync(&Ct[(wm * 32 + i * 16) * CT_LD + j * 16],
                                                fc[i][j], CT_LD, wmma::mem_row_major);
            }
            __syncthreads();
            int c = tid & 63, rg = tid >> 6;
            int gcol = bn * 128 + hh * 64 + c;
            float bias_c = bias[gcol];
            float kvs = g_kv_sum[b * DQ + gcol];
            #pragma unroll 8
            for (int r = rg; r < 128; r += 4) {
                float x = Ct[r * CT_LD + c] + bias_c;
                outp[(size_t)(br * 128 + r) * DQ + gcol] = phi_fn(x) * kvs;
            }
        }
    }
}

// ---------------- deterministic reduction of per-tile partials ----------------
__global__ void kvreduce_kernel() {
    int t = blockIdx.x * 256 + threadIdx.x;
    if (t >= BQ * DQ) return;
    int b = t >> 10, c = t & 1023;
    const float* p = g_partial + (size_t)(b * 64) * DQ + c;
    float s = 0.f;
    #pragma unroll 8
    for (int j = 0; j < 64; j++) s += p[(size_t)j * DQ];
    g_kv_sum[t] = s;
}

// ---------------- entry point ----------------
extern "C" void kernel_launch(void* const* d_in, const int* in_sizes, int n_in,
                              void* d_out, int out_size) {
    const float* query = (const float*)d_in[0];
    const void*  mask  = d_in[1];
    const float* Wq    = (const float*)d_in[2];
    const float* bq    = (const float*)d_in[3];
    const float* Wk    = (const float*)d_in[4];
    const float* bk    = (const float*)d_in[5];
    const float* Wv    = (const float*)d_in[6];
    const float* bv    = (const float*)d_in[7];
    float* out = (float*)d_out;

    const int sv_smem = NHQ * DQ * 4;   // 64KB
    cudaFuncSetAttribute(sv_kernel, cudaFuncAttributeMaxDynamicSharedMemorySize, sv_smem);
    cudaFuncSetAttribute(gemm_kernel<0>, cudaFuncAttributeMaxDynamicSharedMemorySize, GSMEM_B);
    cudaFuncSetAttribute(gemm_kernel<1>, cudaFuncAttributeMaxDynamicSharedMemorySize, GSMEM_B);

    detect_mask_kernel<<<1, 256>>>((const unsigned int*)mask);
    normalize_mask_kernel<<<MT / 256, 256>>>(mask);
    wvsum_kernel<<<(DQ * NHQ + 255) / 256, 256>>>(Wv, bv);
    sv_kernel<<<MT / 32, 256, sv_smem>>>(query);
    gemm_kernel<0><<<dim3(COL_TILES, ROW_TILES), 256, GSMEM_B>>>(query, Wk, bk, nullptr);
    kvreduce_kernel<<<(BQ * DQ + 255) / 256, 256>>>();
    gemm_kernel<1><<<dim3(COL_TILES, ROW_TILES), 256, GSMEM_B>>>(query, Wq, bq, out);
}

// round 13
// speedup vs baseline: 3.3109x; 1.1482x over previous
#include <cuda_runtime.h>
#include <cuda_fp16.h>
#include <mma.h>
#include <cstdint>

using namespace nvcuda;

// NOTE (environment pitfalls, confirmed):
//  - Harness PTX targets sm_103 (no 'a'): tcgen05/TMEM rejected by ptxas.
//    Legacy mma.sync (HMMA) is the usable tensor engine.
//  - 142MB of static __device__ globals poisoned rounds 2/3. This round
//    tests 68MB (fp16 X copy + fp16 weights). If rel_err 0.937 returns,
//    the threshold is bracketed: revert g_Xh.
//  - Winning GEMM shape: 8 warps, 128x128 tile, 4x2 warp grid, double
//    buffered sync loads, 2 CTAs/SM, fp16 operands + fp32 accum.

// ---------------- problem constants ----------------
#define BQ 4
#define LQ 8192
#define DQ 1024
#define NHQ 16
#define HDQ 64
#define MT (BQ * LQ)          // 32768 rows
#define ROW_TILES (MT / 128)  // 256
#define COL_TILES (DQ / 128)  // 8
#define NT 64                 // k-stages of 16

// ---------------- device scratch (no allocations allowed) ----------------
__device__ __align__(16) __half g_Xh[MT * DQ];       // fp16 copy of query (64MB)
__device__ __align__(16) __half g_Wkh[DQ * DQ];      // fp16 Wk (2MB)
__device__ __align__(16) __half g_Wqh[DQ * DQ];      // fp16 Wq (2MB)
__device__ __align__(16) float g_Wv_sumT[NHQ * DQ];  // [head][k]
__device__ __align__(16) float g_bv_sum[NHQ];
__device__ __align__(16) int   g_mask[MT];
__device__ int   g_mask_kind;
__device__ __align__(16) float g_sv[MT * NHQ];
__device__ __align__(16) float g_partial[ROW_TILES * DQ];
__device__ __align__(16) float g_kv_sum[BQ * DQ];

__device__ __forceinline__ float phi_fn(float x) {
    return x > 0.f ? x + 1.f : __expf(x);   // elu(x)+1
}

// ---------------- fp32 -> fp16 conversion (8 elems/thread) ----------------
__global__ void tohalf_kernel(const float* __restrict__ src, __half* __restrict__ dst) {
    int i = blockIdx.x * 256 + threadIdx.x;
    float4 a = ((const float4*)src)[i * 2];
    float4 b = ((const float4*)src)[i * 2 + 1];
    __half2 h0 = __floats2half2_rn(a.x, a.y);
    __half2 h1 = __floats2half2_rn(a.z, a.w);
    __half2 h2 = __floats2half2_rn(b.x, b.y);
    __half2 h3 = __floats2half2_rn(b.z, b.w);
    uint4 u;
    u.x = *reinterpret_cast<const uint32_t*>(&h0);
    u.y = *reinterpret_cast<const uint32_t*>(&h1);
    u.z = *reinterpret_cast<const uint32_t*>(&h2);
    u.w = *reinterpret_cast<const uint32_t*>(&h3);
    ((uint4*)dst)[i] = u;
}

// ---------------- mask dtype detection + normalization ----------------
__global__ void detect_mask_kernel(const unsigned int* m) {
    __shared__ int f_nonbin, f_float;
    if (threadIdx.x == 0) { f_nonbin = 0; f_float = 0; }
    __syncthreads();
    int nb = 0, fl = 0;
    for (int i = threadIdx.x; i < 8192; i += 256) {
        unsigned v = m[i];
        if (v == 0x3F800000u) fl = 1;
        else if (v > 1u) nb = 1;
    }
    if (fl) atomicOr(&f_float, 1);
    if (nb) atomicOr(&f_nonbin, 1);
    __syncthreads();
    if (threadIdx.x == 0) g_mask_kind = f_float ? 2 : (f_nonbin ? 1 : 0);
}

__global__ void normalize_mask_kernel(const void* m) {
    int i = blockIdx.x * 256 + threadIdx.x;
    if (i >= MT) return;
    int kind = g_mask_kind;
    int v;
    if (kind == 2)      v = (((const float*)m)[i] != 0.0f);
    else if (kind == 1) v = (((const unsigned char*)m)[i] != 0);
    else                v = (((const int*)m)[i] != 0);
    g_mask[i] = v;
}

// ---------------- Wv column sums per head (transposed) ----------------
__global__ void wvsum_kernel(const float* __restrict__ Wv,
                             const float* __restrict__ bv) {
    int t = blockIdx.x * 256 + threadIdx.x;
    if (t < DQ * NHQ) {
        int k = t >> 4, n = t & 15;
        const float* p = Wv + (size_t)k * DQ + n * HDQ;
        float s = 0.f;
        #pragma unroll 8
        for (int v = 0; v < HDQ; v++) s += p[v];
        g_Wv_sumT[n * DQ + k] = s;
    }
    if (t < NHQ) {
        const float* p = bv + t * HDQ;
        float s = 0.f;
        #pragma unroll 8
        for (int v = 0; v < HDQ; v++) s += p[v];
        g_bv_sum[t] = s;
    }
}

// ---------------- sv pre-pass: 2 rows/warp for occupancy ----------------
__global__ void __launch_bounds__(256) sv_kernel(const float* __restrict__ X) {
    extern __shared__ __align__(16) float4 sWv[];
    const int tid = threadIdx.x;
    {
        const float4* src = (const float4*)g_Wv_sumT;
        #pragma unroll
        for (int i = 0; i < NHQ * DQ / 4 / 256; i++)
            sWv[i * 256 + tid] = src[i * 256 + tid];
    }
    __syncthreads();

    const int warp = tid >> 5, lane = tid & 31;
    const int row0 = blockIdx.x * 16 + warp * 2;
    const float4* x0 = (const float4*)(X + (size_t)row0 * DQ);
    const float4* x1 = (const float4*)(X + (size_t)(row0 + 1) * DQ);

    float acc[2][NHQ];
    #pragma unroll
    for (int p = 0; p < 2; p++)
        #pragma unroll
        for (int h = 0; h < NHQ; h++) acc[p][h] = 0.f;

    for (int c = lane; c < DQ / 4; c += 32) {
        float4 xv0 = x0[c], xv1 = x1[c];
        #pragma unroll
        for (int h = 0; h < NHQ; h++) {
            float4 w = sWv[h * (DQ / 4) + c];
            acc[0][h] += xv0.x * w.x + xv0.y * w.y + xv0.z * w.z + xv0.w * w.w;
            acc[1][h] += xv1.x * w.x + xv1.y * w.y + xv1.z * w.z + xv1.w * w.w;
        }
    }
    #pragma unroll
    for (int off = 16; off; off >>= 1)
        #pragma unroll
        for (int p = 0; p < 2; p++)
            #pragma unroll
            for (int h = 0; h < NHQ; h++)
                acc[p][h] += __shfl_xor_sync(0xffffffffu, acc[p][h], off);
    if (lane < NHQ) {
        float bvs = g_bv_sum[lane];
        #pragma unroll
        for (int p = 0; p < 2; p++) {
            int m = g_mask[row0 + p];
            g_sv[(size_t)(row0 + p) * NHQ + lane] = m ? 0.f : acc[p][lane] + bvs;
        }
    }
}

// ---------------- main GEMM: 128x128 tile, fp16 HMMA, fp16 gmem operands ---
#define AS_LDH 24
#define BS_LDH 136
#define A_STG_H (128 * AS_LDH)               // 3072 halves
#define B_STG_H (16 * BS_LDH)                // 2176 halves
#define B_BASE_H (2 * A_STG_H)               // 6144
#define CT_LD 68
#define GSMEM_B (128 * CT_LD * 4)            // 34816 B (union covers stages)

template <int MODE>
__global__ void __launch_bounds__(256, 2)
gemm_kernel(const __half* __restrict__ Xh, const __half* __restrict__ Wh,
            const float* __restrict__ bias, float* __restrict__ outp) {
    extern __shared__ __align__(16) char ds[];
    __half* hs = (__half*)ds;            // stages
    float*  Ct = (float*)ds;             // epilogue union
    __shared__ float svred[256];
    __shared__ float red2[256];

    const int tid = threadIdx.x;
    const int bn = blockIdx.x;   // column tile (128 cols = 2 heads)
    const int br = blockIdx.y;   // row tile

    const __half* Ab = Xh + (size_t)br * 128 * DQ;
    const __half* Bb = Wh + bn * 128;

    // A staging: thread owns row arow, 8 halves at aseg
    const int arow = tid >> 1, aseg = (tid & 1) * 8;
    // B staging: thread owns row brow, 8 halves at bseg
    const int brow = tid >> 4, bseg = (tid & 15) * 8;
    const __half* srcA = Ab + (size_t)arow * DQ + aseg;
    const __half* srcB = Bb + (size_t)brow * DQ + bseg;
    __half* dstA = hs + arow * AS_LDH + aseg;
    __half* dstB = hs + B_BASE_H + brow * BS_LDH + bseg;

    const int wid = tid >> 5;
    const int wm = wid & 3;       // warp rows wm*32 .. +31
    const int wn = wid >> 2;      // warp cols wn*64 .. +63

    wmma::fragment<wmma::accumulator, 16, 16, 16, float> fc[2][4];
    #pragma unroll
    for (int i = 0; i < 2; i++)
        #pragma unroll
        for (int j = 0; j < 4; j++)
            wmma::fill_fragment(fc[i][j], 0.f);

    // ---- preload stage 0 ----
    {
        uint4 a = *(const uint4*)(srcA);
        uint4 b = *(const uint4*)(srcB);
        *(uint4*)dstA = a;
        *(uint4*)dstB = b;
    }
    __syncthreads();

    int buf = 0;
    for (int t = 0; t < NT; t++) {
        uint4 na, nb;
        if (t < NT - 1) {
            const int ko = (t + 1) * 16;
            na = *(const uint4*)(srcA + ko);
            nb = *(const uint4*)(srcB + (size_t)ko * DQ);
        }

        // compute on stage[buf]: one K=16 wmma step
        {
            const __half* As = hs + buf * A_STG_H;
            const __half* Bs = hs + B_BASE_H + buf * B_STG_H;
            wmma::fragment<wmma::matrix_a, 16, 16, 16, __half, wmma::row_major> fa[2];
            wmma::fragment<wmma::matrix_b, 16, 16, 16, __half, wmma::row_major> fb[4];
            #pragma unroll
            for (int i = 0; i < 2; i++)
                wmma::load_matrix_sync(fa[i], As + (wm * 32 + i * 16) * AS_LDH, AS_LDH);
            #pragma unroll
            for (int j = 0; j < 4; j++)
                wmma::load_matrix_sync(fb[j], Bs + wn * 64 + j * 16, BS_LDH);
            #pragma unroll
            for (int i = 0; i < 2; i++)
                #pragma unroll
                for (int j = 0; j < 4; j++)
                    wmma::mma_sync(fc[i][j], fa[i], fb[j], fc[i][j]);
        }

        if (t < NT - 1) {
            const int nbuf = buf ^ 1;
            *(uint4*)(dstA + nbuf * A_STG_H) = na;
            *(uint4*)(dstB + nbuf * B_STG_H) = nb;
        }
        __syncthreads();
        buf ^= 1;
    }

    // ---- epilogue (identical math to round 12) ----
    if (MODE == 0) {
        if (tid < 128) {
            float2 s = *(const float2*)(g_sv + (size_t)(br * 128 + tid) * NHQ + bn * 2);
            svred[tid * 2 + 0] = s.x;
            svred[tid * 2 + 1] = s.y;
        }
        #pragma unroll
        for (int hh = 0; hh < 2; hh++) {
            __syncthreads();
            if (wn == hh) {
                #pragma unroll
                for (int i = 0; i < 2; i++)
                    #pragma unroll
                    for (int j = 0; j < 4; j++)
                        wmma::store_matrix_sync(&Ct[(wm * 32 + i * 16) * CT_LD + j * 16],
                                                fc[i][j], CT_LD, wmma::mem_row_major);
            }
            __syncthreads();
            int c = tid & 63, rg = tid >> 6;
            float bias_c = bias[bn * 128 + hh * 64 + c];
            float part = 0.f;
            #pragma unroll 8
            for (int r = rg; r < 128; r += 4) {
                float x = Ct[r * CT_LD + c] + bias_c;
                part += phi_fn(x) * svred[r * 2 + hh];
            }
            red2[rg * 64 + c] = part;
            __syncthreads();
            if (tid < 64) {
                float tot = red2[tid] + red2[64 + tid] + red2[128 + tid] + red2[192 + tid];
                g_partial[(size_t)br * DQ + bn * 128 + hh * 64 + tid] = tot;
            }
        }
    } else {
        int b = br >> 6;
        #pragma unroll
        for (int hh = 0; hh < 2; hh++) {
            __syncthreads();
            if (wn == hh) {
                #pragma unroll
                for (int i = 0; i < 2; i++)
                    #pragma unroll
                    for (int j = 0; j < 4; j++)
                        wmma::store_matrix_sync(&Ct[(wm * 32 + i * 16) * CT_LD + j * 16],
                                                fc[i][j], CT_LD, wmma::mem_row_major);
            }
            __syncthreads();
            int c = tid & 63, rg = tid >> 6;
            int gcol = bn * 128 + hh * 64 + c;
            float bias_c = bias[gcol];
            float kvs = g_kv_sum[b * DQ + gcol];
            #pragma unroll 8
            for (int r = rg; r < 128; r += 4) {
                float x = Ct[r * CT_LD + c] + bias_c;
                outp[(size_t)(br * 128 + r) * DQ + gcol] = phi_fn(x) * kvs;
            }
        }
    }
}

// ---------------- deterministic reduction of per-tile partials ----------------
__global__ void kvreduce_kernel() {
    int t = blockIdx.x * 256 + threadIdx.x;
    if (t >= BQ * DQ) return;
    int b = t >> 10, c = t & 1023;
    const float* p = g_partial + (size_t)(b * 64) * DQ + c;
    float s = 0.f;
    #pragma unroll 8
    for (int j = 0; j < 64; j++) s += p[(size_t)j * DQ];
    g_kv_sum[t] = s;
}

// ---------------- entry point ----------------
extern "C" void kernel_launch(void* const* d_in, const int* in_sizes, int n_in,
                              void* d_out, int out_size) {
    const float* query = (const float*)d_in[0];
    const void*  mask  = d_in[1];
    const float* Wq    = (const float*)d_in[2];
    const float* bq    = (const float*)d_in[3];
    const float* Wk    = (const float*)d_in[4];
    const float* bk    = (const float*)d_in[5];
    const float* Wv    = (const float*)d_in[6];
    const float* bv    = (const float*)d_in[7];
    float* out = (float*)d_out;

    __half* xh;  cudaGetSymbolAddress((void**)&xh,  g_Xh);
    __half* wkh; cudaGetSymbolAddress((void**)&wkh, g_Wkh);
    __half* wqh; cudaGetSymbolAddress((void**)&wqh, g_Wqh);

    const int sv_smem = NHQ * DQ * 4;   // 64KB
    cudaFuncSetAttribute(sv_kernel, cudaFuncAttributeMaxDynamicSharedMemorySize, sv_smem);
    cudaFuncSetAttribute(gemm_kernel<0>, cudaFuncAttributeMaxDynamicSharedMemorySize, GSMEM_B);
    cudaFuncSetAttribute(gemm_kernel<1>, cudaFuncAttributeMaxDynamicSharedMemorySize, GSMEM_B);

    detect_mask_kernel<<<1, 256>>>((const unsigned int*)mask);
    normalize_mask_kernel<<<MT / 256, 256>>>(mask);
    wvsum_kernel<<<(DQ * NHQ + 255) / 256, 256>>>(Wv, bv);
    tohalf_kernel<<<MT * DQ / 8 / 256, 256>>>(query, xh);
    tohalf_kernel<<<DQ * DQ / 8 / 256, 256>>>(Wk, wkh);
    tohalf_kernel<<<DQ * DQ / 8 / 256, 256>>>(Wq, wqh);
    sv_kernel<<<MT / 16, 256, sv_smem>>>(query);
    gemm_kernel<0><<<dim3(COL_TILES, ROW_TILES), 256, GSMEM_B>>>(xh, wkh, bk, nullptr);
    kvreduce_kernel<<<(BQ * DQ + 255) / 256, 256>>>();
    gemm_kernel<1><<<dim3(COL_TILES, ROW_TILES), 256, GSMEM_B>>>(xh, wqh, bq, out);
}